// round 11
// baseline (speedup 1.0000x reference)
#include <cuda_runtime.h>
#include <cuda_fp16.h>
#include <math.h>
#include <stdint.h>

// Problem constants
#define B_   4
#define L_   2048
#define DIM_ 1024
#define DFF_ 4096
#define NTOK (B_ * L_)            // 8192 rows
#define CS   32                    // conv chunk size
#define NC   (L_ / CS)             // 64 chunks

// -------- scratch (static __device__ — no allocations allowed) --------
__device__ float   g_y  [(size_t)NTOK * DIM_];
__device__ __half  g_h2h[(size_t)NTOK * DIM_];   // LN2 out, fp16
__device__ __half  g_act[(size_t)NTOK * DFF_];   // SiLU out, fp16
__device__ __half  g_w1h[(size_t)DFF_ * DIM_];   // w1^T fp16 [N=4096,K=1024]
__device__ __half  g_w2h[(size_t)DIM_ * DFF_];   // w2^T fp16 [N=1024,K=4096]
__device__ float2  g_stat[NTOK];                 // LN1 (mu, rstd) per row
__device__ float2  g_carry[B_ * NC * DIM_];
__device__ float2  g_zin  [B_ * NC * DIM_];

// ================= helpers =================
__device__ __forceinline__ uint32_t smem_u32(const void* p) {
    return (uint32_t)__cvta_generic_to_shared(p);
}
__device__ __forceinline__ void cp_async16(uint32_t saddr, const void* gptr) {
    asm volatile("cp.async.cg.shared.global [%0], [%1], 16;" :: "r"(saddr), "l"(gptr));
}
#define CP_COMMIT()  asm volatile("cp.async.commit_group;" ::: "memory")
#define CP_WAIT(n)   asm volatile("cp.async.wait_group %0;" :: "n"(n) : "memory")
#define LDSM_X4(r0, r1, r2, r3, addr) \
    asm volatile("ldmatrix.sync.aligned.m8n8.x4.shared.b16 {%0,%1,%2,%3}, [%4];" \
                 : "=r"(r0), "=r"(r1), "=r"(r2), "=r"(r3) : "r"(addr))

// per-thread phazor math (replaces phazor_prep kernel)
__device__ __forceinline__ void phazor_compute(const float* __restrict__ phazor,
                                               int d, float2& p, float2& p32) {
    float pr = phazor[2 * d], pim = phazor[2 * d + 1];
    float pa = sqrtf(pr * pr + pim * pim);
    float s = __expf(-pa) / pa;
    p = make_float2(pr * s, pim * s);
    float2 q = p;
    #pragma unroll
    for (int i = 0; i < 5; i++) {
        float nr = q.x * q.x - q.y * q.y;
        q.y = 2.f * q.x * q.y;
        q.x = nr;
    }
    p32 = q;
}

// ========== conv phase1 (fused LN1 stats + scan carry) ==========
__global__ void conv_phase1(const float* __restrict__ x, const float* __restrict__ lng,
                            const float* __restrict__ lnb,
                            const float* __restrict__ phazor) {
    __shared__ float2 sh_stat[CS];
    int b = blockIdx.x >> 6, c = blockIdx.x & 63;
    int tid = threadIdx.x;
    int row0 = b * L_ + c * CS;

    // ---- pass A: stats (warp per row) ----
    {
        int j = tid >> 5, lane = tid & 31;
        const float4* xr = (const float4*)(x + (size_t)(row0 + j) * DIM_);
        float s = 0.f, ss = 0.f;
        #pragma unroll
        for (int i = 0; i < 8; i++) {
            float4 v = xr[lane + 32 * i];
            s  += v.x + v.y + v.z + v.w;
            ss += v.x * v.x + v.y * v.y + v.z * v.z + v.w * v.w;
        }
        #pragma unroll
        for (int o = 16; o > 0; o >>= 1) {
            s  += __shfl_xor_sync(0xffffffffu, s, o);
            ss += __shfl_xor_sync(0xffffffffu, ss, o);
        }
        if (lane == 0) {
            float mu = s * (1.f / DIM_);
            float var = ss * (1.f / DIM_) - mu * mu;
            float2 st = make_float2(mu, rsqrtf(var + 1e-5f));
            sh_stat[j] = st;
            g_stat[row0 + j] = st;
        }
    }
    __syncthreads();

    // ---- pass B: scan ----
    int d = tid;
    float2 p, p32;
    phazor_compute(phazor, d, p, p32);
    float gd = lng[d], bd = lnb[d];
    float zr = 0.f, zi = 0.f;
    const float* xp = x + (size_t)row0 * DIM_ + d;
    #pragma unroll 8
    for (int j = 0; j < CS; j++) {
        float2 st = sh_stat[j];
        float hv = (xp[(size_t)j * DIM_] - st.x) * st.y * gd + bd;
        float nr = p.x * zr - p.y * zi + hv;
        zi = p.x * zi + p.y * zr;
        zr = nr;
    }
    g_carry[(b * NC + c) * DIM_ + d] = make_float2(zr, zi);
}

// ========== conv phase2: exclusive prefix across 64 chunks ==========
__global__ void conv_phase2(const float* __restrict__ phazor) {
    int b = blockIdx.x;
    int d = blockIdx.y * 256 + threadIdx.x;
    float2 p, pc;
    phazor_compute(phazor, d, p, pc);
    float zr = 0.f, zi = 0.f;
    #pragma unroll
    for (int half = 0; half < 2; half++) {
        float2 cv[32];
        #pragma unroll
        for (int i = 0; i < 32; i++)
            cv[i] = g_carry[(b * NC + half * 32 + i) * DIM_ + d];
        #pragma unroll
        for (int i = 0; i < 32; i++) {
            g_zin[(b * NC + half * 32 + i) * DIM_ + d] = make_float2(zr, zi);
            float nr = pc.x * zr - pc.y * zi + cv[i].x;
            zi = pc.x * zi + pc.y * zr + cv[i].y;
            zr = nr;
        }
    }
}

// ========== conv phase3 (scan -> y) + fused LN2 (y -> h2h fp16) ==========
__global__ void conv_phase3(const float* __restrict__ x, const float* __restrict__ lng,
                            const float* __restrict__ lnb,
                            const float* __restrict__ phazor,
                            const float* __restrict__ phazor_init,
                            const float* __restrict__ lre, const float* __restrict__ lim,
                            float* __restrict__ y, __half* __restrict__ h2h) {
    __shared__ float2 sh2[CS];
    int b = blockIdx.x >> 6, c = blockIdx.x & 63;
    int tid = threadIdx.x;
    int row0 = b * L_ + c * CS;

    // ---- pass A: scan, emit y = conv + past + x ----
    {
        int d = tid;
        float2 p, pc;
        phazor_compute(phazor, d, p, pc);
        float2 pi = make_float2(phazor_init[2 * d], phazor_init[2 * d + 1]);
        float2 z  = g_zin[(b * NC + c) * DIM_ + d];
        float gd = lng[d], bd = lnb[d];
        float twr = 1.f, twi = 0.f;
        for (int i = 0; i < c; i++) {
            float nr = twr * pc.x - twi * pc.y;
            twi = twr * pc.y + twi * pc.x;
            twr = nr;
        }
        float pwr = twr * p.x - twi * p.y;
        float pwi = twr * p.y + twi * p.x;
        float lr = lre[b * DIM_ + d], li = lim[b * DIM_ + d];
        size_t base = (size_t)row0 * DIM_ + d;
        #pragma unroll 8
        for (int j = 0; j < CS; j++) {
            float xv = x[base + (size_t)j * DIM_];
            float2 st = g_stat[row0 + j];
            float hv = (xv - st.x) * st.y * gd + bd;
            float nr = p.x * z.x - p.y * z.y + hv;
            z.y = p.x * z.y + p.y * z.x;
            z.x = nr;
            float val = pi.x * z.x - pi.y * z.y + lr * pwr - li * pwi;
            y[base + (size_t)j * DIM_] = val + xv;
            float npr = pwr * p.x - pwi * p.y;
            pwi = pwr * p.y + pwi * p.x;
            pwr = npr;
        }
    }
    __syncthreads();

    // ---- pass B: LN2 stats (warp per row, y from hot L2) ----
    int j = tid >> 5, lane = tid & 31;
    const float4* yr = (const float4*)(y + (size_t)(row0 + j) * DIM_);
    {
        float s = 0.f, ss = 0.f;
        #pragma unroll
        for (int i = 0; i < 8; i++) {
            float4 v = yr[lane + 32 * i];
            s  += v.x + v.y + v.z + v.w;
            ss += v.x * v.x + v.y * v.y + v.z * v.z + v.w * v.w;
        }
        #pragma unroll
        for (int o = 16; o > 0; o >>= 1) {
            s  += __shfl_xor_sync(0xffffffffu, s, o);
            ss += __shfl_xor_sync(0xffffffffu, ss, o);
        }
        if (lane == 0) {
            float mu = s * (1.f / DIM_);
            float var = ss * (1.f / DIM_) - mu * mu;
            sh2[j] = make_float2(mu, rsqrtf(var + 1e-5f));
        }
    }
    __syncthreads();

    // ---- pass C: apply LN2, emit h2h fp16 ----
    {
        float2 st = sh2[j];
        float mu = st.x, inv = st.y;
        #pragma unroll
        for (int i = 0; i < 8; i++) {
            float4 v  = yr[lane + 32 * i];
            float4 gv = ((const float4*)lng)[lane + 32 * i];
            float4 bv = ((const float4*)lnb)[lane + 32 * i];
            __half2 h0 = __floats2half2_rn((v.x - mu) * inv * gv.x + bv.x,
                                           (v.y - mu) * inv * gv.y + bv.y);
            __half2 h1 = __floats2half2_rn((v.z - mu) * inv * gv.z + bv.z,
                                           (v.w - mu) * inv * gv.w + bv.w);
            uint2 pk = make_uint2(*(uint32_t*)&h0, *(uint32_t*)&h1);
            *(uint2*)(h2h + (size_t)(row0 + j) * DIM_ + (lane + 32 * i) * 4) = pk;
        }
    }
}

// ======== weight transpose + cast ([K,N] fp32 -> [N,K] fp16) ========
__global__ void transpose_h(const float* __restrict__ in, __half* __restrict__ out,
                            int R, int Ccols) {
    __shared__ float t[32][33];
    int bx = blockIdx.x * 32, by = blockIdx.y * 32;
    int tx = threadIdx.x, ty = threadIdx.y;
    #pragma unroll
    for (int j = 0; j < 32; j += 8)
        t[ty + j][tx] = in[(size_t)(by + ty + j) * Ccols + bx + tx];
    __syncthreads();
    #pragma unroll
    for (int j = 0; j < 32; j += 8)
        out[(size_t)(bx + ty + j) * R + by + tx] = __float2half(t[tx][ty + j]);
}

// ======= fp16 tensor-core GEMM (mma.sync m16n8k16 + ldmatrix) =======
// CTA tile 128 x CTN, 2 CTAs/SM, BK=32, 8 warps (2x4), 3-stage ring.
// EPI==0: act(half) = silu(acc + bias)             (full-K)
// EPI==2: atomicAdd(out, acc [+ bias + res if z0])  (split-K, klen per z)
#define TBK 32
#define ROW_H 72                         // padded stride in halves (144B)

template <int EPI, int CTN>
__global__ __launch_bounds__(256, 2) void hgemm(
    const __half* __restrict__ A, const __half* __restrict__ Bt,
    const float* __restrict__ bias, const float* __restrict__ res,
    __half* __restrict__ Ch, float* __restrict__ Cf,
    int M, int N, int K, int klen) {
    constexpr int WNW = CTN / 4;         // warp n-width
    constexpr int NT  = WNW / 8;         // n-subtiles
    constexpr int NP  = NT / 2;          // ldmatrix x4 B loads
    constexpr int BCH = CTN / 64;        // B 16B-chunks per thread
    constexpr int A_H = 128 * ROW_H;
    constexpr int STG = (128 + CTN) * ROW_H;

    extern __shared__ __half sm[];
    int tid = threadIdx.x, wid = tid >> 5, lane = tid & 31;
    int g = lane >> 2, l4 = lane & 3;
    int wm = (wid & 1) * 64;
    int wn = (wid >> 1) * WNW;
    int bm = blockIdx.y * 128, bn = blockIdx.x * CTN;
    int kbeg = blockIdx.z * klen;
    const int NK = klen / TBK;

    int mat = lane >> 3, rr = lane & 7;
    uint32_t aoff[4], boff[NP];
    #pragma unroll
    for (int mt = 0; mt < 4; mt++)
        aoff[mt] = (uint32_t)((wm + mt * 16 + (mat & 1) * 8 + rr) * 144 + (mat >> 1) * 16);
    #pragma unroll
    for (int np = 0; np < NP; np++)
        boff[np] = (uint32_t)((wn + np * 16 + (mat >> 1) * 8 + rr) * 144 + (mat & 1) * 16);

    auto load_stage = [&](int s, int k0) {
        uint32_t base = smem_u32(sm + (size_t)s * STG);
        #pragma unroll
        for (int i = 0; i < 2; i++) {
            int c = tid + i * 256;
            int row = c >> 2, kc = c & 3;
            cp_async16(base + row * 144 + kc * 16,
                       A + (size_t)(bm + row) * K + kbeg + k0 + kc * 8);
        }
        uint32_t bb = base + A_H * 2;
        #pragma unroll
        for (int i = 0; i < BCH; i++) {
            int c = tid + i * 256;
            int row = c >> 2, kc = c & 3;
            cp_async16(bb + row * 144 + kc * 16,
                       Bt + (size_t)(bn + row) * K + kbeg + k0 + kc * 8);
        }
    };

    float acc[4][NT][4];
    #pragma unroll
    for (int i = 0; i < 4; i++)
        #pragma unroll
        for (int j = 0; j < NT; j++)
            #pragma unroll
            for (int r = 0; r < 4; r++) acc[i][j][r] = 0.f;

    load_stage(0, 0);       CP_COMMIT();
    load_stage(1, TBK);     CP_COMMIT();

    for (int kt = 0; kt < NK; kt++) {
        if (kt + 1 < NK) CP_WAIT(1); else CP_WAIT(0);
        __syncthreads();
        if (kt + 2 < NK) load_stage((kt + 2) % 3, (kt + 2) * TBK);
        CP_COMMIT();
        uint32_t sa = smem_u32(sm + (size_t)(kt % 3) * STG);
        uint32_t sb = sa + A_H * 2;
        #pragma unroll
        for (int ks = 0; ks < TBK; ks += 16) {
            uint32_t af[4][4], bf[NT][2];
            #pragma unroll
            for (int mt = 0; mt < 4; mt++)
                LDSM_X4(af[mt][0], af[mt][1], af[mt][2], af[mt][3],
                        sa + aoff[mt] + ks * 2);
            #pragma unroll
            for (int np = 0; np < NP; np++)
                LDSM_X4(bf[2 * np][0], bf[2 * np][1], bf[2 * np + 1][0], bf[2 * np + 1][1],
                        sb + boff[np] + ks * 2);
            #pragma unroll
            for (int mt = 0; mt < 4; mt++)
                #pragma unroll
                for (int nt = 0; nt < NT; nt++) {
                    asm volatile(
                        "mma.sync.aligned.m16n8k16.row.col.f32.f16.f16.f32 "
                        "{%0,%1,%2,%3}, {%4,%5,%6,%7}, {%8,%9}, {%0,%1,%2,%3};"
                        : "+f"(acc[mt][nt][0]), "+f"(acc[mt][nt][1]),
                          "+f"(acc[mt][nt][2]), "+f"(acc[mt][nt][3])
                        : "r"(af[mt][0]), "r"(af[mt][1]), "r"(af[mt][2]), "r"(af[mt][3]),
                          "r"(bf[nt][0]), "r"(bf[nt][1]));
                }
        }
    }

    // ---- epilogue ----
    #pragma unroll
    for (int mt = 0; mt < 4; mt++) {
        int r0 = bm + wm + mt * 16 + g;
        #pragma unroll
        for (int nt = 0; nt < NT; nt++) {
            int col = bn + wn + nt * 8 + 2 * l4;
            float bv0 = bias[col], bv1 = bias[col + 1];
            #pragma unroll
            for (int h = 0; h < 2; h++) {
                int row = r0 + h * 8;
                size_t off = (size_t)row * N + col;
                float v0 = acc[mt][nt][2 * h + 0];
                float v1 = acc[mt][nt][2 * h + 1];
                if (EPI == 0) {
                    v0 += bv0; v1 += bv1;
                    v0 = v0 / (1.f + __expf(-v0));
                    v1 = v1 / (1.f + __expf(-v1));
                    __half2 hv = __floats2half2_rn(v0, v1);
                    *(__half2*)&Ch[off] = hv;
                } else {
                    if (blockIdx.z == 0) {
                        v0 += bv0 + res[off];
                        v1 += bv1 + res[off + 1];
                    }
                    atomicAdd(&Cf[off],     v0);
                    atomicAdd(&Cf[off + 1], v1);
                }
            }
        }
    }
}

// ================= launch =================
extern "C" void kernel_launch(void* const* d_in, const int* in_sizes, int n_in,
                              void* d_out, int out_size) {
    const float* x      = (const float*)d_in[0];
    const float* ln_g   = (const float*)d_in[1];
    const float* ln_b   = (const float*)d_in[2];
    const float* phazor = (const float*)d_in[3];
    const float* phinit = (const float*)d_in[4];
    const float* w1     = (const float*)d_in[5];
    const float* b1     = (const float*)d_in[6];
    const float* w2     = (const float*)d_in[7];
    const float* b2     = (const float*)d_in[8];
    const float* lre    = (const float*)d_in[9];
    const float* lim    = (const float*)d_in[10];
    float* out = (float*)d_out;

    float *y;
    __half *h2h, *act, *w1h, *w2h;
    cudaGetSymbolAddress((void**)&y,   g_y);
    cudaGetSymbolAddress((void**)&h2h, g_h2h);
    cudaGetSymbolAddress((void**)&act, g_act);
    cudaGetSymbolAddress((void**)&w1h, g_w1h);
    cudaGetSymbolAddress((void**)&w2h, g_w2h);

    const int SMEM1 = 3 * (128 + 128) * ROW_H * 2;   // 110592
    const int SMEM2 = 3 * (128 + 64) * ROW_H * 2;    // 82944
    cudaFuncSetAttribute((hgemm<0,128>), cudaFuncAttributeMaxDynamicSharedMemorySize, SMEM1);
    cudaFuncSetAttribute((hgemm<2,64>),  cudaFuncAttributeMaxDynamicSharedMemorySize, SMEM2);

    // side stream: zero out + weight transposes, overlapping the conv chain.
    // (Objects persist — bounded leak; destroying capture-referenced objects
    // mid-capture is illegal.)
    cudaStream_t s2;
    cudaStreamCreateWithFlags(&s2, cudaStreamNonBlocking);
    cudaEvent_t evRoot, evT;
    cudaEventCreateWithFlags(&evRoot, cudaEventDisableTiming);
    cudaEventCreateWithFlags(&evT,    cudaEventDisableTiming);

    cudaEventRecord(evRoot, 0);
    cudaStreamWaitEvent(s2, evRoot, 0);

    cudaMemsetAsync(out, 0, (size_t)NTOK * DIM_ * sizeof(float), s2);
    transpose_h<<<dim3(DFF_ / 32, DIM_ / 32), dim3(32, 8), 0, s2>>>(w1, w1h, DIM_, DFF_);
    transpose_h<<<dim3(DIM_ / 32, DFF_ / 32), dim3(32, 8), 0, s2>>>(w2, w2h, DFF_, DIM_);
    cudaEventRecord(evT, s2);

    // main: conv scan (LN1 fused into phase1, LN2 fused into phase3)
    conv_phase1<<<B_ * NC, DIM_>>>(x, ln_g, ln_b, phazor);
    conv_phase2<<<dim3(B_, DIM_ / 256), 256>>>(phazor);
    conv_phase3<<<B_ * NC, DIM_>>>(x, ln_g, ln_b, phazor, phinit, lre, lim, y, h2h);

    // join: GEMMs need transposed weights (+ zeroed out for split-K GEMM2)
    cudaStreamWaitEvent(0, evT, 0);

    dim3 g1(DFF_ / 128, NTOK / 128, 1);   // 32 x 64
    hgemm<0,128><<<g1, 256, SMEM1>>>(h2h, w1h, b1, nullptr, act, nullptr,
                                     NTOK, DFF_, DIM_, DIM_);
    dim3 g2(DIM_ / 64, NTOK / 128, 2);    // 16 x 64 x 2 = 2048 work units
    hgemm<2,64><<<g2, 256, SMEM2>>>(act, w2h, b2, y, nullptr, out,
                                    NTOK, DIM_, DFF_, DFF_ / 2);
}

// round 12
// speedup vs baseline: 1.0969x; 1.0969x over previous
#include <cuda_runtime.h>
#include <cuda_fp16.h>
#include <math.h>
#include <stdint.h>

// Problem constants
#define B_   4
#define L_   2048
#define DIM_ 1024
#define DFF_ 4096
#define NTOK (B_ * L_)            // 8192 rows
#define CS   32                    // conv chunk size
#define NC   (L_ / CS)             // 64 chunks

// -------- scratch (static __device__ — no allocations allowed) --------
__device__ float   g_y  [(size_t)NTOK * DIM_];
__device__ __half  g_h2h[(size_t)NTOK * DIM_];   // LN2 out, fp16
__device__ __half  g_act[(size_t)NTOK * DFF_];   // SiLU out, fp16
__device__ __half  g_w1h[(size_t)DFF_ * DIM_];   // w1^T fp16 [N=4096,K=1024]
__device__ __half  g_w2h[(size_t)DIM_ * DFF_];   // w2^T fp16 [N=1024,K=4096]
__device__ float2  g_stat[NTOK];                 // LN1 (mu, rstd) per row
__device__ float2  g_carry[B_ * NC * DIM_];
__device__ float2  g_zin  [B_ * NC * DIM_];

// ================= helpers =================
__device__ __forceinline__ uint32_t smem_u32(const void* p) {
    return (uint32_t)__cvta_generic_to_shared(p);
}
__device__ __forceinline__ void cp_async16(uint32_t saddr, const void* gptr) {
    asm volatile("cp.async.cg.shared.global [%0], [%1], 16;" :: "r"(saddr), "l"(gptr));
}
#define CP_COMMIT()  asm volatile("cp.async.commit_group;" ::: "memory")
#define CP_WAIT(n)   asm volatile("cp.async.wait_group %0;" :: "n"(n) : "memory")
#define LDSM_X4(r0, r1, r2, r3, addr) \
    asm volatile("ldmatrix.sync.aligned.m8n8.x4.shared.b16 {%0,%1,%2,%3}, [%4];" \
                 : "=r"(r0), "=r"(r1), "=r"(r2), "=r"(r3) : "r"(addr))

// per-thread phazor math
__device__ __forceinline__ void phazor_compute(const float* __restrict__ phazor,
                                               int d, float2& p, float2& p32) {
    float pr = phazor[2 * d], pim = phazor[2 * d + 1];
    float pa = sqrtf(pr * pr + pim * pim);
    float s = __expf(-pa) / pa;
    p = make_float2(pr * s, pim * s);
    float2 q = p;
    #pragma unroll
    for (int i = 0; i < 5; i++) {
        float nr = q.x * q.x - q.y * q.y;
        q.y = 2.f * q.x * q.y;
        q.x = nr;
    }
    p32 = q;
}

// ========== conv phase1 (fused LN1 stats + scan carry) ==========
__global__ void conv_phase1(const float* __restrict__ x, const float* __restrict__ lng,
                            const float* __restrict__ lnb,
                            const float* __restrict__ phazor) {
    __shared__ float2 sh_stat[CS];
    int b = blockIdx.x >> 6, c = blockIdx.x & 63;
    int tid = threadIdx.x;
    int row0 = b * L_ + c * CS;

    // ---- pass A: stats (warp per row) ----
    {
        int j = tid >> 5, lane = tid & 31;
        const float4* xr = (const float4*)(x + (size_t)(row0 + j) * DIM_);
        float s = 0.f, ss = 0.f;
        #pragma unroll
        for (int i = 0; i < 8; i++) {
            float4 v = xr[lane + 32 * i];
            s  += v.x + v.y + v.z + v.w;
            ss += v.x * v.x + v.y * v.y + v.z * v.z + v.w * v.w;
        }
        #pragma unroll
        for (int o = 16; o > 0; o >>= 1) {
            s  += __shfl_xor_sync(0xffffffffu, s, o);
            ss += __shfl_xor_sync(0xffffffffu, ss, o);
        }
        if (lane == 0) {
            float mu = s * (1.f / DIM_);
            float var = ss * (1.f / DIM_) - mu * mu;
            float2 st = make_float2(mu, rsqrtf(var + 1e-5f));
            sh_stat[j] = st;
            g_stat[row0 + j] = st;
        }
    }
    __syncthreads();

    // ---- pass B: scan ----
    int d = tid;
    float2 p, p32;
    phazor_compute(phazor, d, p, p32);
    float gd = lng[d], bd = lnb[d];
    float zr = 0.f, zi = 0.f;
    const float* xp = x + (size_t)row0 * DIM_ + d;
    #pragma unroll 8
    for (int j = 0; j < CS; j++) {
        float2 st = sh_stat[j];
        float hv = (xp[(size_t)j * DIM_] - st.x) * st.y * gd + bd;
        float nr = p.x * zr - p.y * zi + hv;
        zi = p.x * zi + p.y * zr;
        zr = nr;
    }
    g_carry[(b * NC + c) * DIM_ + d] = make_float2(zr, zi);
}

// ========== conv phase2: warp-parallel affine scan over 64 chunks ==========
// One warp per (b,d) chain. Element i: z -> pc*z + carry_i (affine (m,v)).
// 2 chunks/lane, 5-step Hillis-Steele inclusive scan, exclusive shift.
__global__ void conv_phase2(const float* __restrict__ phazor) {
    int wid = threadIdx.x >> 5, lane = threadIdx.x & 31;
    int ci = blockIdx.x * 8 + wid;          // 0..4095 chain id
    int b = ci >> 10, d = ci & 1023;
    float2 p, pc;
    phazor_compute(phazor, d, p, pc);

    int c0 = 2 * lane, c1 = 2 * lane + 1;
    float2 e0 = g_carry[(b * NC + c0) * DIM_ + d];
    float2 e1 = g_carry[(b * NC + c1) * DIM_ + d];

    // segment combine (2 chunks): m = pc^2, v = pc*e0 + e1
    float mr = pc.x * pc.x - pc.y * pc.y;
    float mi = 2.f * pc.x * pc.y;
    float vr = pc.x * e0.x - pc.y * e0.y + e1.x;
    float vi = pc.x * e0.y + pc.y * e0.x + e1.y;

    // inclusive scan across 32 segments
    #pragma unroll
    for (int o = 1; o < 32; o <<= 1) {
        float pmr = __shfl_up_sync(0xffffffffu, mr, o);
        float pmi = __shfl_up_sync(0xffffffffu, mi, o);
        float pvr = __shfl_up_sync(0xffffffffu, vr, o);
        float pvi = __shfl_up_sync(0xffffffffu, vi, o);
        if (lane >= o) {
            float nvr = mr * pvr - mi * pvi + vr;     // v = m_own*v_prev + v_own
            float nvi = mr * pvi + mi * pvr + vi;
            float nmr = mr * pmr - mi * pmi;          // m = m_own*m_prev
            float nmi = mr * pmi + mi * pmr;
            vr = nvr; vi = nvi; mr = nmr; mi = nmi;
        }
    }

    // exclusive shift: z_in[c0] = inclusive value of previous lane
    float zvr = __shfl_up_sync(0xffffffffu, vr, 1);
    float zvi = __shfl_up_sync(0xffffffffu, vi, 1);
    if (lane == 0) { zvr = 0.f; zvi = 0.f; }
    g_zin[(b * NC + c0) * DIM_ + d] = make_float2(zvr, zvi);
    float z1r = pc.x * zvr - pc.y * zvi + e0.x;       // advance one chunk
    float z1i = pc.x * zvi + pc.y * zvr + e0.y;
    g_zin[(b * NC + c1) * DIM_ + d] = make_float2(z1r, z1i);
}

// ========== conv phase3 (scan -> y) + fused LN2 (y -> h2h fp16) ==========
__global__ void conv_phase3(const float* __restrict__ x, const float* __restrict__ lng,
                            const float* __restrict__ lnb,
                            const float* __restrict__ phazor,
                            const float* __restrict__ phazor_init,
                            const float* __restrict__ lre, const float* __restrict__ lim,
                            float* __restrict__ y, __half* __restrict__ h2h) {
    __shared__ float2 sh2[CS];
    int b = blockIdx.x >> 6, c = blockIdx.x & 63;
    int tid = threadIdx.x;
    int row0 = b * L_ + c * CS;

    // ---- pass A: scan, emit y = conv + past + x ----
    {
        int d = tid;
        float2 p, pc;
        phazor_compute(phazor, d, p, pc);
        float2 pi = make_float2(phazor_init[2 * d], phazor_init[2 * d + 1]);
        float2 z  = g_zin[(b * NC + c) * DIM_ + d];
        float gd = lng[d], bd = lnb[d];
        float twr = 1.f, twi = 0.f;
        for (int i = 0; i < c; i++) {
            float nr = twr * pc.x - twi * pc.y;
            twi = twr * pc.y + twi * pc.x;
            twr = nr;
        }
        float pwr = twr * p.x - twi * p.y;
        float pwi = twr * p.y + twi * p.x;
        float lr = lre[b * DIM_ + d], li = lim[b * DIM_ + d];
        size_t base = (size_t)row0 * DIM_ + d;
        #pragma unroll 8
        for (int j = 0; j < CS; j++) {
            float xv = x[base + (size_t)j * DIM_];
            float2 st = g_stat[row0 + j];
            float hv = (xv - st.x) * st.y * gd + bd;
            float nr = p.x * z.x - p.y * z.y + hv;
            z.y = p.x * z.y + p.y * z.x;
            z.x = nr;
            float val = pi.x * z.x - pi.y * z.y + lr * pwr - li * pwi;
            y[base + (size_t)j * DIM_] = val + xv;
            float npr = pwr * p.x - pwi * p.y;
            pwi = pwr * p.y + pwi * p.x;
            pwr = npr;
        }
    }
    __syncthreads();

    // ---- pass B: LN2 stats (warp per row, y from hot L2) ----
    int j = tid >> 5, lane = tid & 31;
    const float4* yr = (const float4*)(y + (size_t)(row0 + j) * DIM_);
    {
        float s = 0.f, ss = 0.f;
        #pragma unroll
        for (int i = 0; i < 8; i++) {
            float4 v = yr[lane + 32 * i];
            s  += v.x + v.y + v.z + v.w;
            ss += v.x * v.x + v.y * v.y + v.z * v.z + v.w * v.w;
        }
        #pragma unroll
        for (int o = 16; o > 0; o >>= 1) {
            s  += __shfl_xor_sync(0xffffffffu, s, o);
            ss += __shfl_xor_sync(0xffffffffu, ss, o);
        }
        if (lane == 0) {
            float mu = s * (1.f / DIM_);
            float var = ss * (1.f / DIM_) - mu * mu;
            sh2[j] = make_float2(mu, rsqrtf(var + 1e-5f));
        }
    }
    __syncthreads();

    // ---- pass C: apply LN2, emit h2h fp16 ----
    {
        float2 st = sh2[j];
        float mu = st.x, inv = st.y;
        #pragma unroll
        for (int i = 0; i < 8; i++) {
            float4 v  = yr[lane + 32 * i];
            float4 gv = ((const float4*)lng)[lane + 32 * i];
            float4 bv = ((const float4*)lnb)[lane + 32 * i];
            __half2 h0 = __floats2half2_rn((v.x - mu) * inv * gv.x + bv.x,
                                           (v.y - mu) * inv * gv.y + bv.y);
            __half2 h1 = __floats2half2_rn((v.z - mu) * inv * gv.z + bv.z,
                                           (v.w - mu) * inv * gv.w + bv.w);
            uint2 pk = make_uint2(*(uint32_t*)&h0, *(uint32_t*)&h1);
            *(uint2*)(h2h + (size_t)(row0 + j) * DIM_ + (lane + 32 * i) * 4) = pk;
        }
    }
}

// ======== weight transpose + cast ([K,N] fp32 -> [N,K] fp16) ========
__global__ void transpose_h(const float* __restrict__ in, __half* __restrict__ out,
                            int R, int Ccols) {
    __shared__ float t[32][33];
    int bx = blockIdx.x * 32, by = blockIdx.y * 32;
    int tx = threadIdx.x, ty = threadIdx.y;
    #pragma unroll
    for (int j = 0; j < 32; j += 8)
        t[ty + j][tx] = in[(size_t)(by + ty + j) * Ccols + bx + tx];
    __syncthreads();
    #pragma unroll
    for (int j = 0; j < 32; j += 8)
        out[(size_t)(bx + ty + j) * R + by + tx] = __float2half(t[tx][ty + j]);
}

// ======= fp16 tensor-core GEMM (mma.sync m16n8k16 + ldmatrix) =======
// CTA tile 128x128, 2 CTAs/SM, BK=32, 8 warps (2x4), warp tile 64x32,
// 3-stage cp.async ring, 1 barrier per k-tile.
// EPI==0: act(half) = silu(acc + bias);  EPI==1: out(f32) = acc + bias + res
#define TBK 32
#define ROW_H 72                         // padded stride in halves (144B)
#define CTN 128
#define GEMM_SMEM (3 * (128 + CTN) * ROW_H * 2)   // 110592

template <int EPI>
__global__ __launch_bounds__(256, 2) void hgemm(
    const __half* __restrict__ A, const __half* __restrict__ Bt,
    const float* __restrict__ bias, const float* __restrict__ res,
    __half* __restrict__ Ch, float* __restrict__ Cf, int M, int N, int K) {
    constexpr int WNW = CTN / 4;         // 32
    constexpr int NT  = WNW / 8;         // 4
    constexpr int NP  = NT / 2;          // 2
    constexpr int BCH = CTN / 64;        // 2
    constexpr int A_H = 128 * ROW_H;
    constexpr int STG = (128 + CTN) * ROW_H;

    extern __shared__ __half sm[];
    int tid = threadIdx.x, wid = tid >> 5, lane = tid & 31;
    int g = lane >> 2, l4 = lane & 3;
    int wm = (wid & 1) * 64;
    int wn = (wid >> 1) * WNW;
    int bm = blockIdx.y * 128, bn = blockIdx.x * CTN;
    const int NK = K / TBK;

    int mat = lane >> 3, rr = lane & 7;
    uint32_t aoff[4], boff[NP];
    #pragma unroll
    for (int mt = 0; mt < 4; mt++)
        aoff[mt] = (uint32_t)((wm + mt * 16 + (mat & 1) * 8 + rr) * 144 + (mat >> 1) * 16);
    #pragma unroll
    for (int np = 0; np < NP; np++)
        boff[np] = (uint32_t)((wn + np * 16 + (mat >> 1) * 8 + rr) * 144 + (mat & 1) * 16);

    auto load_stage = [&](int s, int k0) {
        uint32_t base = smem_u32(sm + (size_t)s * STG);
        #pragma unroll
        for (int i = 0; i < 2; i++) {
            int c = tid + i * 256;
            int row = c >> 2, kc = c & 3;
            cp_async16(base + row * 144 + kc * 16,
                       A + (size_t)(bm + row) * K + k0 + kc * 8);
        }
        uint32_t bb = base + A_H * 2;
        #pragma unroll
        for (int i = 0; i < BCH; i++) {
            int c = tid + i * 256;
            int row = c >> 2, kc = c & 3;
            cp_async16(bb + row * 144 + kc * 16,
                       Bt + (size_t)(bn + row) * K + k0 + kc * 8);
        }
    };

    float acc[4][NT][4];
    #pragma unroll
    for (int i = 0; i < 4; i++)
        #pragma unroll
        for (int j = 0; j < NT; j++)
            #pragma unroll
            for (int r = 0; r < 4; r++) acc[i][j][r] = 0.f;

    load_stage(0, 0);       CP_COMMIT();
    load_stage(1, TBK);     CP_COMMIT();

    for (int kt = 0; kt < NK; kt++) {
        if (kt + 1 < NK) CP_WAIT(1); else CP_WAIT(0);
        __syncthreads();
        if (kt + 2 < NK) load_stage((kt + 2) % 3, (kt + 2) * TBK);
        CP_COMMIT();
        uint32_t sa = smem_u32(sm + (size_t)(kt % 3) * STG);
        uint32_t sb = sa + A_H * 2;
        #pragma unroll
        for (int ks = 0; ks < TBK; ks += 16) {
            uint32_t af[4][4], bf[NT][2];
            #pragma unroll
            for (int mt = 0; mt < 4; mt++)
                LDSM_X4(af[mt][0], af[mt][1], af[mt][2], af[mt][3],
                        sa + aoff[mt] + ks * 2);
            #pragma unroll
            for (int np = 0; np < NP; np++)
                LDSM_X4(bf[2 * np][0], bf[2 * np][1], bf[2 * np + 1][0], bf[2 * np + 1][1],
                        sb + boff[np] + ks * 2);
            #pragma unroll
            for (int mt = 0; mt < 4; mt++)
                #pragma unroll
                for (int nt = 0; nt < NT; nt++) {
                    asm volatile(
                        "mma.sync.aligned.m16n8k16.row.col.f32.f16.f16.f32 "
                        "{%0,%1,%2,%3}, {%4,%5,%6,%7}, {%8,%9}, {%0,%1,%2,%3};"
                        : "+f"(acc[mt][nt][0]), "+f"(acc[mt][nt][1]),
                          "+f"(acc[mt][nt][2]), "+f"(acc[mt][nt][3])
                        : "r"(af[mt][0]), "r"(af[mt][1]), "r"(af[mt][2]), "r"(af[mt][3]),
                          "r"(bf[nt][0]), "r"(bf[nt][1]));
                }
        }
    }

    // ---- epilogue ----
    #pragma unroll
    for (int mt = 0; mt < 4; mt++) {
        int r0 = bm + wm + mt * 16 + g;
        #pragma unroll
        for (int nt = 0; nt < NT; nt++) {
            int col = bn + wn + nt * 8 + 2 * l4;
            float bv0 = bias[col], bv1 = bias[col + 1];
            #pragma unroll
            for (int h = 0; h < 2; h++) {
                int row = r0 + h * 8;
                size_t off = (size_t)row * N + col;
                float v0 = acc[mt][nt][2 * h + 0] + bv0;
                float v1 = acc[mt][nt][2 * h + 1] + bv1;
                if (EPI == 0) {
                    v0 = v0 / (1.f + __expf(-v0));
                    v1 = v1 / (1.f + __expf(-v1));
                    __half2 hv = __floats2half2_rn(v0, v1);
                    *(__half2*)&Ch[off] = hv;
                } else {
                    v0 += res[off];
                    v1 += res[off + 1];
                    *(float2*)&Cf[off] = make_float2(v0, v1);
                }
            }
        }
    }
}

// ================= launch =================
extern "C" void kernel_launch(void* const* d_in, const int* in_sizes, int n_in,
                              void* d_out, int out_size) {
    const float* x      = (const float*)d_in[0];
    const float* ln_g   = (const float*)d_in[1];
    const float* ln_b   = (const float*)d_in[2];
    const float* phazor = (const float*)d_in[3];
    const float* phinit = (const float*)d_in[4];
    const float* w1     = (const float*)d_in[5];
    const float* b1     = (const float*)d_in[6];
    const float* w2     = (const float*)d_in[7];
    const float* b2     = (const float*)d_in[8];
    const float* lre    = (const float*)d_in[9];
    const float* lim    = (const float*)d_in[10];
    float* out = (float*)d_out;

    float *y;
    __half *h2h, *act, *w1h, *w2h;
    cudaGetSymbolAddress((void**)&y,   g_y);
    cudaGetSymbolAddress((void**)&h2h, g_h2h);
    cudaGetSymbolAddress((void**)&act, g_act);
    cudaGetSymbolAddress((void**)&w1h, g_w1h);
    cudaGetSymbolAddress((void**)&w2h, g_w2h);

    cudaFuncSetAttribute(hgemm<0>, cudaFuncAttributeMaxDynamicSharedMemorySize, GEMM_SMEM);
    cudaFuncSetAttribute(hgemm<1>, cudaFuncAttributeMaxDynamicSharedMemorySize, GEMM_SMEM);

    // side stream: weight transposes overlap the conv chain, join before GEMM1.
    // (Objects persist — bounded leak; destroying capture-referenced objects
    // mid-capture is illegal.)
    cudaStream_t s2;
    cudaStreamCreateWithFlags(&s2, cudaStreamNonBlocking);
    cudaEvent_t evRoot, evT;
    cudaEventCreateWithFlags(&evRoot, cudaEventDisableTiming);
    cudaEventCreateWithFlags(&evT,    cudaEventDisableTiming);

    cudaEventRecord(evRoot, 0);
    cudaStreamWaitEvent(s2, evRoot, 0);

    transpose_h<<<dim3(DFF_ / 32, DIM_ / 32), dim3(32, 8), 0, s2>>>(w1, w1h, DIM_, DFF_);
    transpose_h<<<dim3(DIM_ / 32, DFF_ / 32), dim3(32, 8), 0, s2>>>(w2, w2h, DFF_, DIM_);
    cudaEventRecord(evT, s2);

    // main: conv scan (LN1 fused into phase1, LN2 fused into phase3)
    conv_phase1<<<B_ * NC, DIM_>>>(x, ln_g, ln_b, phazor);
    conv_phase2<<<(B_ * DIM_) / 8, 256>>>(phazor);          // 512 blocks, warp/chain
    conv_phase3<<<B_ * NC, DIM_>>>(x, ln_g, ln_b, phazor, phinit, lre, lim, y, h2h);

    // join: GEMMs need the transposed weights
    cudaStreamWaitEvent(0, evT, 0);

    dim3 g1(DFF_ / CTN, NTOK / 128);   // 32 x 64
    hgemm<0><<<g1, 256, GEMM_SMEM>>>(h2h, w1h, b1, nullptr, act, nullptr, NTOK, DFF_, DIM_);
    dim3 g2(DIM_ / CTN, NTOK / 128);   // 8 x 64
    hgemm<1><<<g2, 256, GEMM_SMEM>>>(act, w2h, b2, y, nullptr, out, NTOK, DIM_, DFF_);
}

// round 13
// speedup vs baseline: 1.1151x; 1.0166x over previous
#include <cuda_runtime.h>
#include <cuda_fp16.h>
#include <math.h>
#include <stdint.h>

// Problem constants
#define B_   4
#define L_   2048
#define DIM_ 1024
#define DFF_ 4096
#define NTOK (B_ * L_)            // 8192 rows
#define CS   32                    // conv chunk size
#define NC   (L_ / CS)             // 64 chunks

// -------- scratch (static __device__ — no allocations allowed) --------
__device__ float   g_y  [(size_t)NTOK * DIM_];
__device__ __half  g_h2h[(size_t)NTOK * DIM_];   // LN2 out, fp16
__device__ __half  g_act[(size_t)NTOK * DFF_];   // SiLU out, fp16
__device__ __half  g_w1h[(size_t)DFF_ * DIM_];   // w1^T fp16 [N=4096,K=1024]
__device__ __half  g_w2h[(size_t)DIM_ * DFF_];   // w2^T fp16 [N=1024,K=4096]
__device__ float2  g_stat[NTOK];                 // LN1 (mu, rstd) per row
__device__ float2  g_carry[B_ * NC * DIM_];
__device__ float2  g_zin  [B_ * NC * DIM_];
__device__ float2  g_p    [DIM_];
__device__ float2  g_pinit[DIM_];
__device__ float2  g_p32  [DIM_];
__device__ float2  g_pw   [NC * DIM_];           // p^(c*CS+1) per (c,d)

// ================= helpers =================
__device__ __forceinline__ uint32_t smem_u32(const void* p) {
    return (uint32_t)__cvta_generic_to_shared(p);
}
__device__ __forceinline__ void cp_async16(uint32_t saddr, const void* gptr) {
    asm volatile("cp.async.cg.shared.global [%0], [%1], 16;" :: "r"(saddr), "l"(gptr));
}
#define CP_COMMIT()  asm volatile("cp.async.commit_group;" ::: "memory")
#define CP_WAIT(n)   asm volatile("cp.async.wait_group %0;" :: "n"(n) : "memory")
#define LDSM_X4(r0, r1, r2, r3, addr) \
    asm volatile("ldmatrix.sync.aligned.m8n8.x4.shared.b16 {%0,%1,%2,%3}, [%4];" \
                 : "=r"(r0), "=r"(r1), "=r"(r2), "=r"(r3) : "r"(addr))

// ================= phazor precompute =================
__global__ void phazor_prep(const float* __restrict__ phazor,
                            const float* __restrict__ phazor_init) {
    int d = blockIdx.x * 256 + threadIdx.x;
    if (d >= DIM_) return;
    float pr = phazor[2 * d], pim = phazor[2 * d + 1];
    float pa = sqrtf(pr * pr + pim * pim);
    float s = expf(-pa) / pa;
    float2 p = make_float2(pr * s, pim * s);
    g_p[d] = p;
    g_pinit[d] = make_float2(phazor_init[2 * d], phazor_init[2 * d + 1]);
    float2 q = p;                              // p^32 via 5 squarings
    #pragma unroll
    for (int i = 0; i < 5; i++) {
        float nr = q.x * q.x - q.y * q.y;
        q.y = 2.f * q.x * q.y;
        q.x = nr;
    }
    g_p32[d] = q;
    // pw[c] = p^(c*CS + 1)
    float2 pw = p;
    for (int c = 0; c < NC; c++) {
        g_pw[c * DIM_ + d] = pw;
        float nr = pw.x * q.x - pw.y * q.y;
        pw.y = pw.x * q.y + pw.y * q.x;
        pw.x = nr;
    }
}

// ========== conv phase1 (fused LN1 stats + scan carry) ==========
__global__ void conv_phase1(const float* __restrict__ x, const float* __restrict__ lng,
                            const float* __restrict__ lnb) {
    __shared__ float2 sh_stat[CS];
    int b = blockIdx.x >> 6, c = blockIdx.x & 63;
    int tid = threadIdx.x;
    int row0 = b * L_ + c * CS;

    // ---- pass A: stats (warp per row) ----
    {
        int j = tid >> 5, lane = tid & 31;
        const float4* xr = (const float4*)(x + (size_t)(row0 + j) * DIM_);
        float s = 0.f, ss = 0.f;
        #pragma unroll
        for (int i = 0; i < 8; i++) {
            float4 v = xr[lane + 32 * i];
            s  += v.x + v.y + v.z + v.w;
            ss += v.x * v.x + v.y * v.y + v.z * v.z + v.w * v.w;
        }
        #pragma unroll
        for (int o = 16; o > 0; o >>= 1) {
            s  += __shfl_xor_sync(0xffffffffu, s, o);
            ss += __shfl_xor_sync(0xffffffffu, ss, o);
        }
        if (lane == 0) {
            float mu = s * (1.f / DIM_);
            float var = ss * (1.f / DIM_) - mu * mu;
            float2 st = make_float2(mu, rsqrtf(var + 1e-5f));
            sh_stat[j] = st;
            g_stat[row0 + j] = st;
        }
    }
    __syncthreads();

    // ---- pass B: scan ----
    int d = tid;
    float2 p = g_p[d];
    float gd = lng[d], bd = lnb[d];
    float zr = 0.f, zi = 0.f;
    const float* xp = x + (size_t)row0 * DIM_ + d;
    #pragma unroll 8
    for (int j = 0; j < CS; j++) {
        float2 st = sh_stat[j];
        float hv = (xp[(size_t)j * DIM_] - st.x) * st.y * gd + bd;
        float nr = p.x * zr - p.y * zi + hv;
        zi = p.x * zi + p.y * zr;
        zr = nr;
    }
    g_carry[(b * NC + c) * DIM_ + d] = make_float2(zr, zi);
}

// ========== conv phase2: warp-parallel affine scan over 64 chunks ==========
// One warp per (b,d) chain; 2 chunks/lane; Hillis-Steele shfl scan.
__global__ void conv_phase2() {
    int wid = threadIdx.x >> 5, lane = threadIdx.x & 31;
    int ci = blockIdx.x * 8 + wid;          // 0..4095 chain id
    int b = ci >> 10, d = ci & 1023;
    float2 pc = g_p32[d];

    int c0 = 2 * lane, c1 = 2 * lane + 1;
    float2 e0 = g_carry[(b * NC + c0) * DIM_ + d];
    float2 e1 = g_carry[(b * NC + c1) * DIM_ + d];

    // segment combine (2 chunks): m = pc^2, v = pc*e0 + e1
    float mr = pc.x * pc.x - pc.y * pc.y;
    float mi = 2.f * pc.x * pc.y;
    float vr = pc.x * e0.x - pc.y * e0.y + e1.x;
    float vi = pc.x * e0.y + pc.y * e0.x + e1.y;

    // inclusive scan across 32 segments
    #pragma unroll
    for (int o = 1; o < 32; o <<= 1) {
        float pmr = __shfl_up_sync(0xffffffffu, mr, o);
        float pmi = __shfl_up_sync(0xffffffffu, mi, o);
        float pvr = __shfl_up_sync(0xffffffffu, vr, o);
        float pvi = __shfl_up_sync(0xffffffffu, vi, o);
        if (lane >= o) {
            float nvr = mr * pvr - mi * pvi + vr;
            float nvi = mr * pvi + mi * pvr + vi;
            float nmr = mr * pmr - mi * pmi;
            float nmi = mr * pmi + mi * pmr;
            vr = nvr; vi = nvi; mr = nmr; mi = nmi;
        }
    }

    // exclusive shift
    float zvr = __shfl_up_sync(0xffffffffu, vr, 1);
    float zvi = __shfl_up_sync(0xffffffffu, vi, 1);
    if (lane == 0) { zvr = 0.f; zvi = 0.f; }
    g_zin[(b * NC + c0) * DIM_ + d] = make_float2(zvr, zvi);
    float z1r = pc.x * zvr - pc.y * zvi + e0.x;
    float z1i = pc.x * zvi + pc.y * zvr + e0.y;
    g_zin[(b * NC + c1) * DIM_ + d] = make_float2(z1r, z1i);
}

// ========== conv phase3 (scan -> y) + fused LN2 (y -> h2h fp16) ==========
__global__ void conv_phase3(const float* __restrict__ x, const float* __restrict__ lng,
                            const float* __restrict__ lnb,
                            const float* __restrict__ lre, const float* __restrict__ lim,
                            float* __restrict__ y, __half* __restrict__ h2h) {
    __shared__ float2 sh2[CS];
    int b = blockIdx.x >> 6, c = blockIdx.x & 63;
    int tid = threadIdx.x;
    int row0 = b * L_ + c * CS;

    // ---- pass A: scan, emit y = conv + past + x ----
    {
        int d = tid;
        float2 p  = g_p[d];
        float2 pi = g_pinit[d];
        float2 pw = g_pw[c * DIM_ + d];       // p^(c*CS+1), precomputed
        float2 z  = g_zin[(b * NC + c) * DIM_ + d];
        float gd = lng[d], bd = lnb[d];
        float pwr = pw.x, pwi = pw.y;
        float lr = lre[b * DIM_ + d], li = lim[b * DIM_ + d];
        size_t base = (size_t)row0 * DIM_ + d;
        #pragma unroll 8
        for (int j = 0; j < CS; j++) {
            float xv = x[base + (size_t)j * DIM_];
            float2 st = g_stat[row0 + j];
            float hv = (xv - st.x) * st.y * gd + bd;
            float nr = p.x * z.x - p.y * z.y + hv;
            z.y = p.x * z.y + p.y * z.x;
            z.x = nr;
            float val = pi.x * z.x - pi.y * z.y + lr * pwr - li * pwi;
            y[base + (size_t)j * DIM_] = val + xv;
            float npr = pwr * p.x - pwi * p.y;
            pwi = pwr * p.y + pwi * p.x;
            pwr = npr;
        }
    }
    __syncthreads();

    // ---- pass B: LN2 stats (warp per row, y from hot L2) ----
    int j = tid >> 5, lane = tid & 31;
    const float4* yr = (const float4*)(y + (size_t)(row0 + j) * DIM_);
    {
        float s = 0.f, ss = 0.f;
        #pragma unroll
        for (int i = 0; i < 8; i++) {
            float4 v = yr[lane + 32 * i];
            s  += v.x + v.y + v.z + v.w;
            ss += v.x * v.x + v.y * v.y + v.z * v.z + v.w * v.w;
        }
        #pragma unroll
        for (int o = 16; o > 0; o >>= 1) {
            s  += __shfl_xor_sync(0xffffffffu, s, o);
            ss += __shfl_xor_sync(0xffffffffu, ss, o);
        }
        if (lane == 0) {
            float mu = s * (1.f / DIM_);
            float var = ss * (1.f / DIM_) - mu * mu;
            sh2[j] = make_float2(mu, rsqrtf(var + 1e-5f));
        }
    }
    __syncthreads();

    // ---- pass C: apply LN2, emit h2h fp16 ----
    {
        float2 st = sh2[j];
        float mu = st.x, inv = st.y;
        #pragma unroll
        for (int i = 0; i < 8; i++) {
            float4 v  = yr[lane + 32 * i];
            float4 gv = ((const float4*)lng)[lane + 32 * i];
            float4 bv = ((const float4*)lnb)[lane + 32 * i];
            __half2 h0 = __floats2half2_rn((v.x - mu) * inv * gv.x + bv.x,
                                           (v.y - mu) * inv * gv.y + bv.y);
            __half2 h1 = __floats2half2_rn((v.z - mu) * inv * gv.z + bv.z,
                                           (v.w - mu) * inv * gv.w + bv.w);
            uint2 pk = make_uint2(*(uint32_t*)&h0, *(uint32_t*)&h1);
            *(uint2*)(h2h + (size_t)(row0 + j) * DIM_ + (lane + 32 * i) * 4) = pk;
        }
    }
}

// ======== weight transpose + cast ([K,N] fp32 -> [N,K] fp16) ========
__global__ void transpose_h(const float* __restrict__ in, __half* __restrict__ out,
                            int R, int Ccols) {
    __shared__ float t[32][33];
    int bx = blockIdx.x * 32, by = blockIdx.y * 32;
    int tx = threadIdx.x, ty = threadIdx.y;
    #pragma unroll
    for (int j = 0; j < 32; j += 8)
        t[ty + j][tx] = in[(size_t)(by + ty + j) * Ccols + bx + tx];
    __syncthreads();
    #pragma unroll
    for (int j = 0; j < 32; j += 8)
        out[(size_t)(bx + ty + j) * R + by + tx] = __float2half(t[tx][ty + j]);
}

// ======= fp16 tensor-core GEMM (mma.sync m16n8k16 + ldmatrix) =======
// CTA tile 128x128, 2 CTAs/SM, BK=32, 8 warps (2x4), warp tile 64x32,
// 3-stage cp.async ring, 1 barrier per k-tile.
// EPI==0: act(half) = silu(acc + bias);  EPI==1: out(f32) = acc + bias + res
#define TBK 32
#define ROW_H 72                         // padded stride in halves (144B)
#define CTN 128
#define GEMM_SMEM (3 * (128 + CTN) * ROW_H * 2)   // 110592

template <int EPI>
__global__ __launch_bounds__(256, 2) void hgemm(
    const __half* __restrict__ A, const __half* __restrict__ Bt,
    const float* __restrict__ bias, const float* __restrict__ res,
    __half* __restrict__ Ch, float* __restrict__ Cf, int M, int N, int K) {
    constexpr int WNW = CTN / 4;         // 32
    constexpr int NT  = WNW / 8;         // 4
    constexpr int NP  = NT / 2;          // 2
    constexpr int BCH = CTN / 64;        // 2
    constexpr int A_H = 128 * ROW_H;
    constexpr int STG = (128 + CTN) * ROW_H;

    extern __shared__ __half sm[];
    int tid = threadIdx.x, wid = tid >> 5, lane = tid & 31;
    int g = lane >> 2, l4 = lane & 3;
    int wm = (wid & 1) * 64;
    int wn = (wid >> 1) * WNW;
    int bm = blockIdx.y * 128, bn = blockIdx.x * CTN;
    const int NK = K / TBK;

    int mat = lane >> 3, rr = lane & 7;
    uint32_t aoff[4], boff[NP];
    #pragma unroll
    for (int mt = 0; mt < 4; mt++)
        aoff[mt] = (uint32_t)((wm + mt * 16 + (mat & 1) * 8 + rr) * 144 + (mat >> 1) * 16);
    #pragma unroll
    for (int np = 0; np < NP; np++)
        boff[np] = (uint32_t)((wn + np * 16 + (mat >> 1) * 8 + rr) * 144 + (mat & 1) * 16);

    auto load_stage = [&](int s, int k0) {
        uint32_t base = smem_u32(sm + (size_t)s * STG);
        #pragma unroll
        for (int i = 0; i < 2; i++) {
            int c = tid + i * 256;
            int row = c >> 2, kc = c & 3;
            cp_async16(base + row * 144 + kc * 16,
                       A + (size_t)(bm + row) * K + k0 + kc * 8);
        }
        uint32_t bb = base + A_H * 2;
        #pragma unroll
        for (int i = 0; i < BCH; i++) {
            int c = tid + i * 256;
            int row = c >> 2, kc = c & 3;
            cp_async16(bb + row * 144 + kc * 16,
                       Bt + (size_t)(bn + row) * K + k0 + kc * 8);
        }
    };

    float acc[4][NT][4];
    #pragma unroll
    for (int i = 0; i < 4; i++)
        #pragma unroll
        for (int j = 0; j < NT; j++)
            #pragma unroll
            for (int r = 0; r < 4; r++) acc[i][j][r] = 0.f;

    load_stage(0, 0);       CP_COMMIT();
    load_stage(1, TBK);     CP_COMMIT();

    for (int kt = 0; kt < NK; kt++) {
        if (kt + 1 < NK) CP_WAIT(1); else CP_WAIT(0);
        __syncthreads();
        if (kt + 2 < NK) load_stage((kt + 2) % 3, (kt + 2) * TBK);
        CP_COMMIT();
        uint32_t sa = smem_u32(sm + (size_t)(kt % 3) * STG);
        uint32_t sb = sa + A_H * 2;
        #pragma unroll
        for (int ks = 0; ks < TBK; ks += 16) {
            uint32_t af[4][4], bf[NT][2];
            #pragma unroll
            for (int mt = 0; mt < 4; mt++)
                LDSM_X4(af[mt][0], af[mt][1], af[mt][2], af[mt][3],
                        sa + aoff[mt] + ks * 2);
            #pragma unroll
            for (int np = 0; np < NP; np++)
                LDSM_X4(bf[2 * np][0], bf[2 * np][1], bf[2 * np + 1][0], bf[2 * np + 1][1],
                        sb + boff[np] + ks * 2);
            #pragma unroll
            for (int mt = 0; mt < 4; mt++)
                #pragma unroll
                for (int nt = 0; nt < NT; nt++) {
                    asm volatile(
                        "mma.sync.aligned.m16n8k16.row.col.f32.f16.f16.f32 "
                        "{%0,%1,%2,%3}, {%4,%5,%6,%7}, {%8,%9}, {%0,%1,%2,%3};"
                        : "+f"(acc[mt][nt][0]), "+f"(acc[mt][nt][1]),
                          "+f"(acc[mt][nt][2]), "+f"(acc[mt][nt][3])
                        : "r"(af[mt][0]), "r"(af[mt][1]), "r"(af[mt][2]), "r"(af[mt][3]),
                          "r"(bf[nt][0]), "r"(bf[nt][1]));
                }
        }
    }

    // ---- epilogue ----
    #pragma unroll
    for (int mt = 0; mt < 4; mt++) {
        int r0 = bm + wm + mt * 16 + g;
        #pragma unroll
        for (int nt = 0; nt < NT; nt++) {
            int col = bn + wn + nt * 8 + 2 * l4;
            float bv0 = bias[col], bv1 = bias[col + 1];
            #pragma unroll
            for (int h = 0; h < 2; h++) {
                int row = r0 + h * 8;
                size_t off = (size_t)row * N + col;
                float v0 = acc[mt][nt][2 * h + 0] + bv0;
                float v1 = acc[mt][nt][2 * h + 1] + bv1;
                if (EPI == 0) {
                    v0 = v0 / (1.f + __expf(-v0));
                    v1 = v1 / (1.f + __expf(-v1));
                    __half2 hv = __floats2half2_rn(v0, v1);
                    *(__half2*)&Ch[off] = hv;
                } else {
                    v0 += res[off];
                    v1 += res[off + 1];
                    *(float2*)&Cf[off] = make_float2(v0, v1);
                }
            }
        }
    }
}

// ================= launch =================
extern "C" void kernel_launch(void* const* d_in, const int* in_sizes, int n_in,
                              void* d_out, int out_size) {
    const float* x      = (const float*)d_in[0];
    const float* ln_g   = (const float*)d_in[1];
    const float* ln_b   = (const float*)d_in[2];
    const float* phazor = (const float*)d_in[3];
    const float* phinit = (const float*)d_in[4];
    const float* w1     = (const float*)d_in[5];
    const float* b1     = (const float*)d_in[6];
    const float* w2     = (const float*)d_in[7];
    const float* b2     = (const float*)d_in[8];
    const float* lre    = (const float*)d_in[9];
    const float* lim    = (const float*)d_in[10];
    float* out = (float*)d_out;

    float *y;
    __half *h2h, *act, *w1h, *w2h;
    cudaGetSymbolAddress((void**)&y,   g_y);
    cudaGetSymbolAddress((void**)&h2h, g_h2h);
    cudaGetSymbolAddress((void**)&act, g_act);
    cudaGetSymbolAddress((void**)&w1h, g_w1h);
    cudaGetSymbolAddress((void**)&w2h, g_w2h);

    cudaFuncSetAttribute(hgemm<0>, cudaFuncAttributeMaxDynamicSharedMemorySize, GEMM_SMEM);
    cudaFuncSetAttribute(hgemm<1>, cudaFuncAttributeMaxDynamicSharedMemorySize, GEMM_SMEM);

    // side stream: weight transposes overlap the conv chain, join before GEMM1.
    // (Objects persist — bounded leak; destroying capture-referenced objects
    // mid-capture is illegal.)
    cudaStream_t s2;
    cudaStreamCreateWithFlags(&s2, cudaStreamNonBlocking);
    cudaEvent_t evRoot, evT;
    cudaEventCreateWithFlags(&evRoot, cudaEventDisableTiming);
    cudaEventCreateWithFlags(&evT,    cudaEventDisableTiming);

    cudaEventRecord(evRoot, 0);
    cudaStreamWaitEvent(s2, evRoot, 0);

    transpose_h<<<dim3(DFF_ / 32, DIM_ / 32), dim3(32, 8), 0, s2>>>(w1, w1h, DIM_, DFF_);
    transpose_h<<<dim3(DIM_ / 32, DFF_ / 32), dim3(32, 8), 0, s2>>>(w2, w2h, DFF_, DIM_);
    cudaEventRecord(evT, s2);

    // main: phazor precompute -> conv scan (LN1 fused in p1, LN2 fused in p3)
    phazor_prep<<<DIM_ / 256, 256>>>(phazor, phinit);
    conv_phase1<<<B_ * NC, DIM_>>>(x, ln_g, ln_b);
    conv_phase2<<<(B_ * DIM_) / 8, 256>>>();          // 512 blocks, warp/chain
    conv_phase3<<<B_ * NC, DIM_>>>(x, ln_g, ln_b, lre, lim, y, h2h);

    // join: GEMMs need the transposed weights
    cudaStreamWaitEvent(0, evT, 0);

    dim3 g1(DFF_ / CTN, NTOK / 128);   // 32 x 64
    hgemm<0><<<g1, 256, GEMM_SMEM>>>(h2h, w1h, b1, nullptr, act, nullptr, NTOK, DFF_, DIM_);
    dim3 g2(DIM_ / CTN, NTOK / 128);   // 8 x 64
    hgemm<1><<<g2, 256, GEMM_SMEM>>>(act, w2h, b2, y, nullptr, out, NTOK, DIM_, DFF_);
}

// round 14
// speedup vs baseline: 1.2585x; 1.1286x over previous
#include <cuda_runtime.h>
#include <cuda_fp16.h>
#include <math.h>
#include <stdint.h>

// Problem constants
#define B_   4
#define L_   2048
#define DIM_ 1024
#define DFF_ 4096
#define NTOK (B_ * L_)            // 8192 rows
#define CS   32                    // conv chunk size
#define NC   (L_ / CS)             // 64 chunks

// -------- scratch (static __device__ — no allocations allowed) --------
__device__ float   g_y  [(size_t)NTOK * DIM_];
__device__ __half  g_h2h[(size_t)NTOK * DIM_];   // LN2 out, fp16
__device__ __half  g_act[(size_t)NTOK * DFF_];   // SiLU out, fp16
__device__ __half  g_w1h[(size_t)DFF_ * DIM_];   // w1^T fp16 [N=4096,K=1024]
__device__ __half  g_w2h[(size_t)DIM_ * DFF_];   // w2^T fp16 [N=1024,K=4096]
__device__ float2  g_stat[NTOK];                 // LN1 (mu, rstd) per row
__device__ float2  g_carry[B_ * NC * DIM_];
__device__ float2  g_zin  [B_ * NC * DIM_];
__device__ float2  g_p    [DIM_];
__device__ float2  g_pinit[DIM_];
__device__ float2  g_p32  [DIM_];
__device__ float2  g_pw   [NC * DIM_];           // p^(c*CS+1) per (c,d)

// ================= helpers =================
__device__ __forceinline__ uint32_t smem_u32(const void* p) {
    return (uint32_t)__cvta_generic_to_shared(p);
}
__device__ __forceinline__ void cp_async16(uint32_t saddr, const void* gptr) {
    asm volatile("cp.async.cg.shared.global [%0], [%1], 16;" :: "r"(saddr), "l"(gptr));
}
#define CP_COMMIT()  asm volatile("cp.async.commit_group;" ::: "memory")
#define CP_WAIT(n)   asm volatile("cp.async.wait_group %0;" :: "n"(n) : "memory")
#define LDSM_X4(r0, r1, r2, r3, addr) \
    asm volatile("ldmatrix.sync.aligned.m8n8.x4.shared.b16 {%0,%1,%2,%3}, [%4];" \
                 : "=r"(r0), "=r"(r1), "=r"(r2), "=r"(r3) : "r"(addr))

// ================= phazor precompute =================
__global__ void phazor_prep(const float* __restrict__ phazor,
                            const float* __restrict__ phazor_init) {
    int d = blockIdx.x * 256 + threadIdx.x;
    if (d >= DIM_) return;
    float pr = phazor[2 * d], pim = phazor[2 * d + 1];
    float pa = sqrtf(pr * pr + pim * pim);
    float s = expf(-pa) / pa;
    float2 p = make_float2(pr * s, pim * s);
    g_p[d] = p;
    g_pinit[d] = make_float2(phazor_init[2 * d], phazor_init[2 * d + 1]);
    float2 q = p;                              // p^32 via 5 squarings
    #pragma unroll
    for (int i = 0; i < 5; i++) {
        float nr = q.x * q.x - q.y * q.y;
        q.y = 2.f * q.x * q.y;
        q.x = nr;
    }
    g_p32[d] = q;
    float2 pw = p;                             // pw[c] = p^(c*CS + 1)
    for (int c = 0; c < NC; c++) {
        g_pw[c * DIM_ + d] = pw;
        float nr = pw.x * q.x - pw.y * q.y;
        pw.y = pw.x * q.y + pw.y * q.x;
        pw.x = nr;
    }
}

// ========== conv phase1 (fused LN1 stats + scan carry) ==========
__global__ void conv_phase1(const float* __restrict__ x, const float* __restrict__ lng,
                            const float* __restrict__ lnb) {
    __shared__ float2 sh_stat[CS];
    int b = blockIdx.x >> 6, c = blockIdx.x & 63;
    int tid = threadIdx.x;
    int row0 = b * L_ + c * CS;

    {
        int j = tid >> 5, lane = tid & 31;
        const float4* xr = (const float4*)(x + (size_t)(row0 + j) * DIM_);
        float s = 0.f, ss = 0.f;
        #pragma unroll
        for (int i = 0; i < 8; i++) {
            float4 v = xr[lane + 32 * i];
            s  += v.x + v.y + v.z + v.w;
            ss += v.x * v.x + v.y * v.y + v.z * v.z + v.w * v.w;
        }
        #pragma unroll
        for (int o = 16; o > 0; o >>= 1) {
            s  += __shfl_xor_sync(0xffffffffu, s, o);
            ss += __shfl_xor_sync(0xffffffffu, ss, o);
        }
        if (lane == 0) {
            float mu = s * (1.f / DIM_);
            float var = ss * (1.f / DIM_) - mu * mu;
            float2 st = make_float2(mu, rsqrtf(var + 1e-5f));
            sh_stat[j] = st;
            g_stat[row0 + j] = st;
        }
    }
    __syncthreads();

    int d = tid;
    float2 p = g_p[d];
    float gd = lng[d], bd = lnb[d];
    float zr = 0.f, zi = 0.f;
    const float* xp = x + (size_t)row0 * DIM_ + d;
    #pragma unroll 8
    for (int j = 0; j < CS; j++) {
        float2 st = sh_stat[j];
        float hv = (xp[(size_t)j * DIM_] - st.x) * st.y * gd + bd;
        float nr = p.x * zr - p.y * zi + hv;
        zi = p.x * zi + p.y * zr;
        zr = nr;
    }
    g_carry[(b * NC + c) * DIM_ + d] = make_float2(zr, zi);
}

// ========== conv phase2: warp-parallel affine scan over 64 chunks ==========
__global__ void conv_phase2() {
    int wid = threadIdx.x >> 5, lane = threadIdx.x & 31;
    int ci = blockIdx.x * 8 + wid;
    int b = ci >> 10, d = ci & 1023;
    float2 pc = g_p32[d];

    int c0 = 2 * lane, c1 = 2 * lane + 1;
    float2 e0 = g_carry[(b * NC + c0) * DIM_ + d];
    float2 e1 = g_carry[(b * NC + c1) * DIM_ + d];

    float mr = pc.x * pc.x - pc.y * pc.y;
    float mi = 2.f * pc.x * pc.y;
    float vr = pc.x * e0.x - pc.y * e0.y + e1.x;
    float vi = pc.x * e0.y + pc.y * e0.x + e1.y;

    #pragma unroll
    for (int o = 1; o < 32; o <<= 1) {
        float pmr = __shfl_up_sync(0xffffffffu, mr, o);
        float pmi = __shfl_up_sync(0xffffffffu, mi, o);
        float pvr = __shfl_up_sync(0xffffffffu, vr, o);
        float pvi = __shfl_up_sync(0xffffffffu, vi, o);
        if (lane >= o) {
            float nvr = mr * pvr - mi * pvi + vr;
            float nvi = mr * pvi + mi * pvr + vi;
            float nmr = mr * pmr - mi * pmi;
            float nmi = mr * pmi + mi * pmr;
            vr = nvr; vi = nvi; mr = nmr; mi = nmi;
        }
    }

    float zvr = __shfl_up_sync(0xffffffffu, vr, 1);
    float zvi = __shfl_up_sync(0xffffffffu, vi, 1);
    if (lane == 0) { zvr = 0.f; zvi = 0.f; }
    g_zin[(b * NC + c0) * DIM_ + d] = make_float2(zvr, zvi);
    float z1r = pc.x * zvr - pc.y * zvi + e0.x;
    float z1i = pc.x * zvi + pc.y * zvr + e0.y;
    g_zin[(b * NC + c1) * DIM_ + d] = make_float2(z1r, z1i);
}

// ========== conv phase3 (scan -> y) + fused LN2 (y -> h2h fp16) ==========
__global__ void conv_phase3(const float* __restrict__ x, const float* __restrict__ lng,
                            const float* __restrict__ lnb,
                            const float* __restrict__ lre, const float* __restrict__ lim,
                            float* __restrict__ y, __half* __restrict__ h2h) {
    __shared__ float2 sh2[CS];
    int b = blockIdx.x >> 6, c = blockIdx.x & 63;
    int tid = threadIdx.x;
    int row0 = b * L_ + c * CS;

    {
        int d = tid;
        float2 p  = g_p[d];
        float2 pi = g_pinit[d];
        float2 pw = g_pw[c * DIM_ + d];
        float2 z  = g_zin[(b * NC + c) * DIM_ + d];
        float gd = lng[d], bd = lnb[d];
        float pwr = pw.x, pwi = pw.y;
        float lr = lre[b * DIM_ + d], li = lim[b * DIM_ + d];
        size_t base = (size_t)row0 * DIM_ + d;
        #pragma unroll 8
        for (int j = 0; j < CS; j++) {
            float xv = x[base + (size_t)j * DIM_];
            float2 st = g_stat[row0 + j];
            float hv = (xv - st.x) * st.y * gd + bd;
            float nr = p.x * z.x - p.y * z.y + hv;
            z.y = p.x * z.y + p.y * z.x;
            z.x = nr;
            float val = pi.x * z.x - pi.y * z.y + lr * pwr - li * pwi;
            y[base + (size_t)j * DIM_] = val + xv;
            float npr = pwr * p.x - pwi * p.y;
            pwi = pwr * p.y + pwi * p.x;
            pwr = npr;
        }
    }
    __syncthreads();

    int j = tid >> 5, lane = tid & 31;
    const float4* yr = (const float4*)(y + (size_t)(row0 + j) * DIM_);
    {
        float s = 0.f, ss = 0.f;
        #pragma unroll
        for (int i = 0; i < 8; i++) {
            float4 v = yr[lane + 32 * i];
            s  += v.x + v.y + v.z + v.w;
            ss += v.x * v.x + v.y * v.y + v.z * v.z + v.w * v.w;
        }
        #pragma unroll
        for (int o = 16; o > 0; o >>= 1) {
            s  += __shfl_xor_sync(0xffffffffu, s, o);
            ss += __shfl_xor_sync(0xffffffffu, ss, o);
        }
        if (lane == 0) {
            float mu = s * (1.f / DIM_);
            float var = ss * (1.f / DIM_) - mu * mu;
            sh2[j] = make_float2(mu, rsqrtf(var + 1e-5f));
        }
    }
    __syncthreads();

    {
        float2 st = sh2[j];
        float mu = st.x, inv = st.y;
        #pragma unroll
        for (int i = 0; i < 8; i++) {
            float4 v  = yr[lane + 32 * i];
            float4 gv = ((const float4*)lng)[lane + 32 * i];
            float4 bv = ((const float4*)lnb)[lane + 32 * i];
            __half2 h0 = __floats2half2_rn((v.x - mu) * inv * gv.x + bv.x,
                                           (v.y - mu) * inv * gv.y + bv.y);
            __half2 h1 = __floats2half2_rn((v.z - mu) * inv * gv.z + bv.z,
                                           (v.w - mu) * inv * gv.w + bv.w);
            uint2 pk = make_uint2(*(uint32_t*)&h0, *(uint32_t*)&h1);
            *(uint2*)(h2h + (size_t)(row0 + j) * DIM_ + (lane + 32 * i) * 4) = pk;
        }
    }
}

// ======== weight transpose + cast ([K,N] fp32 -> [N,K] fp16) ========
__global__ void transpose_h(const float* __restrict__ in, __half* __restrict__ out,
                            int R, int Ccols) {
    __shared__ float t[32][33];
    int bx = blockIdx.x * 32, by = blockIdx.y * 32;
    int tx = threadIdx.x, ty = threadIdx.y;
    #pragma unroll
    for (int j = 0; j < 32; j += 8)
        t[ty + j][tx] = in[(size_t)(by + ty + j) * Ccols + bx + tx];
    __syncthreads();
    #pragma unroll
    for (int j = 0; j < 32; j += 8)
        out[(size_t)(bx + ty + j) * R + by + tx] = __float2half(t[tx][ty + j]);
}

// ======= fp16 tensor-core GEMM (mma.sync m16n8k16 + ldmatrix) =======
// CTA tile 128x128, 2 CTAs/SM, BK=64 (rows 128B data / 144B stride), 8 warps
// (2x4), warp tile 64x32, 3-stage cp.async ring, 1 barrier per k-tile.
// EPI==0: act(half) = silu(acc + bias);  EPI==1: out(f32) = acc + bias + res
#define TBK 64
#define ROW_B 144                        // stride in bytes
#define CTN 128
#define STG_B ((128 + CTN) * ROW_B)      // 36864
#define GEMM_SMEM (3 * STG_B)            // 110592

template <int EPI>
__global__ __launch_bounds__(256, 2) void hgemm(
    const __half* __restrict__ A, const __half* __restrict__ Bt,
    const float* __restrict__ bias, const float* __restrict__ res,
    __half* __restrict__ Ch, float* __restrict__ Cf, int M, int N, int K) {
    constexpr int WNW = CTN / 4;         // 32
    constexpr int NT  = WNW / 8;         // 4
    constexpr int NP  = NT / 2;          // 2
    constexpr int A_B = 128 * ROW_B;

    extern __shared__ char smc[];
    int tid = threadIdx.x, wid = tid >> 5, lane = tid & 31;
    int g = lane >> 2, l4 = lane & 3;
    int wm = (wid & 1) * 64;
    int wn = (wid >> 1) * WNW;
    int bm = blockIdx.y * 128, bn = blockIdx.x * CTN;
    const int NK = K / TBK;

    int mat = lane >> 3, rr = lane & 7;
    uint32_t aoff[4], boff[NP];
    #pragma unroll
    for (int mt = 0; mt < 4; mt++)
        aoff[mt] = (uint32_t)((wm + mt * 16 + (mat & 1) * 8 + rr) * ROW_B + (mat >> 1) * 16);
    #pragma unroll
    for (int np = 0; np < NP; np++)
        boff[np] = (uint32_t)((wn + np * 16 + (mat >> 1) * 8 + rr) * ROW_B + (mat & 1) * 16);

    // per stage: A 128 rows x 8 chunks = 1024; B 128 x 8 = 1024; 8 per thread
    auto load_stage = [&](int s, int k0) {
        uint32_t base = smem_u32(smc + (size_t)s * STG_B);
        #pragma unroll
        for (int i = 0; i < 4; i++) {
            int c = tid + i * 256;
            int row = c >> 3, kc = c & 7;
            cp_async16(base + row * ROW_B + kc * 16,
                       A + (size_t)(bm + row) * K + k0 + kc * 8);
        }
        uint32_t bb = base + A_B;
        #pragma unroll
        for (int i = 0; i < 4; i++) {
            int c = tid + i * 256;
            int row = c >> 3, kc = c & 7;
            cp_async16(bb + row * ROW_B + kc * 16,
                       Bt + (size_t)(bn + row) * K + k0 + kc * 8);
        }
    };

    float acc[4][NT][4];
    #pragma unroll
    for (int i = 0; i < 4; i++)
        #pragma unroll
        for (int j = 0; j < NT; j++)
            #pragma unroll
            for (int r = 0; r < 4; r++) acc[i][j][r] = 0.f;

    load_stage(0, 0);       CP_COMMIT();
    load_stage(1, TBK);     CP_COMMIT();

    for (int kt = 0; kt < NK; kt++) {
        if (kt + 1 < NK) CP_WAIT(1); else CP_WAIT(0);
        __syncthreads();
        if (kt + 2 < NK) load_stage((kt + 2) % 3, (kt + 2) * TBK);
        CP_COMMIT();
        uint32_t sa = smem_u32(smc + (size_t)(kt % 3) * STG_B);
        uint32_t sb = sa + A_B;
        #pragma unroll
        for (int ks = 0; ks < TBK; ks += 16) {
            uint32_t af[4][4], bf[NT][2];
            #pragma unroll
            for (int mt = 0; mt < 4; mt++)
                LDSM_X4(af[mt][0], af[mt][1], af[mt][2], af[mt][3],
                        sa + aoff[mt] + ks * 2);
            #pragma unroll
            for (int np = 0; np < NP; np++)
                LDSM_X4(bf[2 * np][0], bf[2 * np][1], bf[2 * np + 1][0], bf[2 * np + 1][1],
                        sb + boff[np] + ks * 2);
            #pragma unroll
            for (int mt = 0; mt < 4; mt++)
                #pragma unroll
                for (int nt = 0; nt < NT; nt++) {
                    asm volatile(
                        "mma.sync.aligned.m16n8k16.row.col.f32.f16.f16.f32 "
                        "{%0,%1,%2,%3}, {%4,%5,%6,%7}, {%8,%9}, {%0,%1,%2,%3};"
                        : "+f"(acc[mt][nt][0]), "+f"(acc[mt][nt][1]),
                          "+f"(acc[mt][nt][2]), "+f"(acc[mt][nt][3])
                        : "r"(af[mt][0]), "r"(af[mt][1]), "r"(af[mt][2]), "r"(af[mt][3]),
                          "r"(bf[nt][0]), "r"(bf[nt][1]));
                }
        }
    }

    // ---- epilogue ----
    #pragma unroll
    for (int mt = 0; mt < 4; mt++) {
        int r0 = bm + wm + mt * 16 + g;
        #pragma unroll
        for (int nt = 0; nt < NT; nt++) {
            int col = bn + wn + nt * 8 + 2 * l4;
            float bv0 = bias[col], bv1 = bias[col + 1];
            #pragma unroll
            for (int h = 0; h < 2; h++) {
                int row = r0 + h * 8;
                size_t off = (size_t)row * N + col;
                float v0 = acc[mt][nt][2 * h + 0] + bv0;
                float v1 = acc[mt][nt][2 * h + 1] + bv1;
                if (EPI == 0) {
                    v0 = v0 / (1.f + __expf(-v0));
                    v1 = v1 / (1.f + __expf(-v1));
                    __half2 hv = __floats2half2_rn(v0, v1);
                    *(__half2*)&Ch[off] = hv;
                } else {
                    v0 += res[off];
                    v1 += res[off + 1];
                    *(float2*)&Cf[off] = make_float2(v0, v1);
                }
            }
        }
    }
}

// ================= launch =================
extern "C" void kernel_launch(void* const* d_in, const int* in_sizes, int n_in,
                              void* d_out, int out_size) {
    const float* x      = (const float*)d_in[0];
    const float* ln_g   = (const float*)d_in[1];
    const float* ln_b   = (const float*)d_in[2];
    const float* phazor = (const float*)d_in[3];
    const float* phinit = (const float*)d_in[4];
    const float* w1     = (const float*)d_in[5];
    const float* b1     = (const float*)d_in[6];
    const float* w2     = (const float*)d_in[7];
    const float* b2     = (const float*)d_in[8];
    const float* lre    = (const float*)d_in[9];
    const float* lim    = (const float*)d_in[10];
    float* out = (float*)d_out;

    float *y;
    __half *h2h, *act, *w1h, *w2h;
    cudaGetSymbolAddress((void**)&y,   g_y);
    cudaGetSymbolAddress((void**)&h2h, g_h2h);
    cudaGetSymbolAddress((void**)&act, g_act);
    cudaGetSymbolAddress((void**)&w1h, g_w1h);
    cudaGetSymbolAddress((void**)&w2h, g_w2h);

    cudaFuncSetAttribute(hgemm<0>, cudaFuncAttributeMaxDynamicSharedMemorySize, GEMM_SMEM);
    cudaFuncSetAttribute(hgemm<1>, cudaFuncAttributeMaxDynamicSharedMemorySize, GEMM_SMEM);

    // side stream for the w1 transpose (overlaps the conv chain) and the w2
    // transpose (overlaps hgemm1 — only hgemm2 needs it).
    // (Objects persist — bounded leak; destroying capture-referenced objects
    // mid-capture is illegal.)
    cudaStream_t s2;
    cudaStreamCreateWithFlags(&s2, cudaStreamNonBlocking);
    cudaEvent_t evRoot, evT1, evG1, evT2;
    cudaEventCreateWithFlags(&evRoot, cudaEventDisableTiming);
    cudaEventCreateWithFlags(&evT1,   cudaEventDisableTiming);
    cudaEventCreateWithFlags(&evG1,   cudaEventDisableTiming);
    cudaEventCreateWithFlags(&evT2,   cudaEventDisableTiming);

    cudaEventRecord(evRoot, 0);
    cudaStreamWaitEvent(s2, evRoot, 0);

    // s2: w1 transpose only (launch #1)
    transpose_h<<<dim3(DFF_ / 32, DIM_ / 32), dim3(32, 8), 0, s2>>>(w1, w1h, DIM_, DFF_);
    cudaEventRecord(evT1, s2);

    // main: phazor precompute -> conv scan (launches #2-#5)
    phazor_prep<<<DIM_ / 256, 256>>>(phazor, phinit);
    conv_phase1<<<B_ * NC, DIM_>>>(x, ln_g, ln_b);
    conv_phase2<<<(B_ * DIM_) / 8, 256>>>();
    conv_phase3<<<B_ * NC, DIM_>>>(x, ln_g, ln_b, lre, lim, y, h2h);

    // main: GEMM1 (launch #6 — ncu -s 5 -c 1 captures this)
    cudaStreamWaitEvent(0, evT1, 0);
    dim3 g1(DFF_ / CTN, NTOK / 128);   // 32 x 64
    hgemm<0><<<g1, 256, GEMM_SMEM>>>(h2h, w1h, b1, nullptr, act, nullptr, NTOK, DFF_, DIM_);
    cudaEventRecord(evG1, 0);

    // s2: w2 transpose concurrent with GEMM1
    transpose_h<<<dim3(DIM_ / 32, DFF_ / 32), dim3(32, 8), 0, s2>>>(w2, w2h, DFF_, DIM_);
    cudaEventRecord(evT2, s2);

    // main: GEMM2 (needs act + w2h)
    cudaStreamWaitEvent(0, evT2, 0);
    dim3 g2(DIM_ / CTN, NTOK / 128);   // 8 x 64
    hgemm<1><<<g2, 256, GEMM_SMEM>>>(act, w2h, b2, y, nullptr, out, NTOK, DIM_, DFF_);
}